// round 3
// baseline (speedup 1.0000x reference)
#include <cuda_runtime.h>
#include <math.h>

#define Bz  48
#define Ez  512
#define Hz  1024
#define Vz  32000
#define Tz  64
#define G3  3072            // 3*H
#define EP1 513             // E+1
#define OPLD 520            // padded ld for o partials
#define BTV (Bz*Tz*Vz)      // 98,304,000
#define NPART 12            // gate split-K parts: 4 for ig (K=128 ea), 8 for hg (K=128 ea)

// ---------------- scratch (static device memory, no allocation) ----------------
__device__ float g_emb[Tz * Bz * Ez];        // emb_t for t=0..63   (6.29 MB)
__device__ float g_h[2][Bz * Hz];            // hidden ping-pong
__device__ float g_peep[Bz * G3];            // latent @ Wp^T + bp  (constant over t)
__device__ float g_gpart[NPART][Bz * G3];    // split-K gate partials (7.1 MB)
__device__ float g_opart[8 * Bz * OPLD];     // split-K partials for o

__device__ __forceinline__ float sigmoidf_(float x) { return 1.f / (1.f + expf(-x)); }

// ---------------- generic 48xN small GEMM tile (M=48 full, tile N=64, BK=16) ----
struct __align__(16) SmemGemm { float As[16][52]; float Ws[16][68]; };

__device__ __forceinline__ void gemm48_tile(
    SmemGemm& sm,
    const float* __restrict__ A, int lda,
    const float* __restrict__ W, int ldw,
    float* __restrict__ C, int ldc,
    const float* __restrict__ bias,
    int N, int n0, int k0, int kc)
{
    int tid = threadIdx.x;
    int tx = tid & 15, ty = tid >> 4;
    float acc[3][4] = {{0.f,0.f,0.f,0.f},{0.f,0.f,0.f,0.f},{0.f,0.f,0.f,0.f}};

    for (int kk = 0; kk < kc; kk += 16) {
        if (tid < 192) {                         // A tile: 48 rows x 16 k
            int r = tid >> 2, kq = tid & 3;
            float4 v = *(const float4*)(A + r * lda + k0 + kk + kq * 4);
            sm.As[kq*4+0][r] = v.x; sm.As[kq*4+1][r] = v.y;
            sm.As[kq*4+2][r] = v.z; sm.As[kq*4+3][r] = v.w;
        }
        {                                        // W tile: 64 rows x 16 k
            int n = tid >> 2, kq = tid & 3;
            int gn = n0 + n;
            float4 v = make_float4(0.f, 0.f, 0.f, 0.f);
            if (gn < N) v = *(const float4*)(W + gn * ldw + k0 + kk + kq * 4);
            sm.Ws[kq*4+0][n] = v.x; sm.Ws[kq*4+1][n] = v.y;
            sm.Ws[kq*4+2][n] = v.z; sm.Ws[kq*4+3][n] = v.w;
        }
        __syncthreads();
        #pragma unroll
        for (int k = 0; k < 16; k++) {
            float a0 = sm.As[k][ty], a1 = sm.As[k][ty+16], a2 = sm.As[k][ty+32];
            float4 bv = *(const float4*)&sm.Ws[k][tx * 4];
            acc[0][0] += a0*bv.x; acc[0][1] += a0*bv.y; acc[0][2] += a0*bv.z; acc[0][3] += a0*bv.w;
            acc[1][0] += a1*bv.x; acc[1][1] += a1*bv.y; acc[1][2] += a1*bv.z; acc[1][3] += a1*bv.w;
            acc[2][0] += a2*bv.x; acc[2][1] += a2*bv.y; acc[2][2] += a2*bv.z; acc[2][3] += a2*bv.w;
        }
        __syncthreads();
    }
    #pragma unroll
    for (int i = 0; i < 3; i++) {
        int r = ty + i * 16;
        #pragma unroll
        for (int j = 0; j < 4; j++) {
            int n = n0 + tx * 4 + j;
            if (n < N) {
                float v = acc[i][j];
                if (bias) v += bias[n];
                C[r * ldc + n] = v;
            }
        }
    }
}

// ---------------- kernels ------------------------------------------------------

// emb_0 = start broadcast; stops[:,0] = 0
__global__ void seed_kernel(const float* __restrict__ start, float* __restrict__ out)
{
    int idx = blockIdx.x * 256 + threadIdx.x;
    if (idx < Bz * Ez) g_emb[idx] = start[idx & (Ez - 1)];
    if (idx < Bz) out[BTV + idx * Tz] = 0.f;
}

// h0 = latent @ W_lh^T + b_lh ; peep = latent @ Wp^T + bp
__global__ void init_kernel(const float* __restrict__ latent,
                            const float* __restrict__ W_lh, const float* __restrict__ b_lh,
                            const float* __restrict__ Wp,   const float* __restrict__ bp)
{
    __shared__ SmemGemm sm;
    if (blockIdx.x < 16)
        gemm48_tile(sm, latent, Hz, W_lh, Hz, g_h[0], Hz, b_lh, Hz, blockIdx.x * 64, 0, Hz);
    else
        gemm48_tile(sm, latent, Hz, Wp, Hz, g_peep, G3, bp, G3, (blockIdx.x - 16) * 64, 0, Hz);
}

// split-K gate partials: p<4 -> ig (K=512 in 4 chunks), p>=4 -> hg (K=1024 in 8 chunks)
__global__ void gates_kernel(int s, const float* __restrict__ Wi, const float* __restrict__ Wh)
{
    __shared__ SmemGemm sm;
    int p = blockIdx.y;
    int n0 = blockIdx.x * 64;
    if (p < 4)
        gemm48_tile(sm, g_emb + s * Bz * Ez, Ez, Wi, Ez,
                    g_gpart[p], G3, nullptr, G3, n0, p * 128, 128);
    else
        gemm48_tile(sm, g_h[s & 1], Hz, Wh, Hz,
                    g_gpart[p], G3, nullptr, G3, n0, (p - 4) * 128, 128);
}

// gate elementwise: reduce partials, compute hy -> h_new
__global__ void hy_kernel(int s, const float* __restrict__ bi, const float* __restrict__ bh)
{
    int idx = blockIdx.x * 256 + threadIdx.x;    // 48*1024 exactly
    int b = idx >> 10, j = idx & 1023;
    const float* h_prev = g_h[s & 1];
    float* h_new = g_h[(s + 1) & 1];
    int base = b * G3;
    float ir = bi[j], ii = bi[Hz + j], in_ = bi[2*Hz + j];
    #pragma unroll
    for (int p = 0; p < 4; p++) {
        ir  += g_gpart[p][base + j];
        ii  += g_gpart[p][base + Hz + j];
        in_ += g_gpart[p][base + 2*Hz + j];
    }
    float hr = bh[j], hi = bh[Hz + j], hn = bh[2*Hz + j];
    #pragma unroll
    for (int p = 4; p < 12; p++) {
        hr += g_gpart[p][base + j];
        hi += g_gpart[p][base + Hz + j];
        hn += g_gpart[p][base + 2*Hz + j];
    }
    float pr = g_peep[base + j], pi = g_peep[base + Hz + j], pn = g_peep[base + 2*Hz + j];
    float r  = sigmoidf_(ir + hr + pr);
    float zi = sigmoidf_(ii + hi + pi);
    float n  = tanhf(in_ + r * hn + pn);
    float h  = h_prev[idx];
    h_new[idx] = n + zi * (h - n);
}

// o = hy @ Wo^T (split-K 8 x 128) -> partials
__global__ void outp_kernel(int s, const float* __restrict__ Wo)
{
    __shared__ SmemGemm sm;
    int kc = blockIdx.y;                          // 0..7
    gemm48_tile(sm, g_h[(s + 1) & 1], Hz, Wo, Hz,
                g_opart + kc * Bz * OPLD, OPLD, nullptr, EP1,
                blockIdx.x * 64, kc * 128, 128);
}

// reduce o partials + bo; tanh -> emb_{s+1}, sigmoid -> stop_{s+1}
__global__ void reduce_kernel(int s, const float* __restrict__ bo, float* __restrict__ out)
{
    int idx = blockIdx.x * 256 + threadIdx.x;
    if (idx >= Bz * EP1) return;
    int b = idx / EP1, n = idx % EP1;
    float v = bo[n];
    #pragma unroll
    for (int k = 0; k < 8; k++) v += g_opart[k * Bz * OPLD + b * OPLD + n];
    int t = s + 1;
    if (n < Ez) g_emb[(t * Bz + b) * Ez + n] = tanhf(v);
    else        out[BTV + b * Tz + t] = sigmoidf_(v);
}

// logits: (T*B, E) @ Wu^T + bu -> out in (B,T,V) layout.
// 128x128x16 SGEMM, 8x8/thread, double-buffered smem.
__global__ void __launch_bounds__(256) unembed_kernel(
    const float* __restrict__ Wu, const float* __restrict__ bu, float* __restrict__ out)
{
    __shared__ __align__(16) float As[2][16][132];
    __shared__ __align__(16) float Bs[2][16][132];
    int bn = blockIdx.x, bm = blockIdx.y;
    int tid = threadIdx.x;
    int tx = tid & 15, ty = tid >> 4;
    const float* A  = g_emb + bm * 128 * Ez;
    const float* Bp = Wu + bn * 128 * Ez;

    // per-thread load coords (2 float4 per operand per tile)
    int r0 = tid >> 2,           kq0 = tid & 3;
    int r1 = (tid + 256) >> 2,   kq1 = tid & 3;   // (tid+256)&3 == tid&3

    float acc[8][8];
    #pragma unroll
    for (int i = 0; i < 8; i++)
        #pragma unroll
        for (int j = 0; j < 8; j++) acc[i][j] = 0.f;

    // preload tile 0 into buffer 0
    {
        float4 va0 = *(const float4*)(A  + r0 * Ez + kq0 * 4);
        float4 vb0 = *(const float4*)(Bp + r0 * Ez + kq0 * 4);
        float4 va1 = *(const float4*)(A  + r1 * Ez + kq1 * 4);
        float4 vb1 = *(const float4*)(Bp + r1 * Ez + kq1 * 4);
        As[0][kq0*4+0][r0]=va0.x; As[0][kq0*4+1][r0]=va0.y; As[0][kq0*4+2][r0]=va0.z; As[0][kq0*4+3][r0]=va0.w;
        Bs[0][kq0*4+0][r0]=vb0.x; Bs[0][kq0*4+1][r0]=vb0.y; Bs[0][kq0*4+2][r0]=vb0.z; Bs[0][kq0*4+3][r0]=vb0.w;
        As[0][kq1*4+0][r1]=va1.x; As[0][kq1*4+1][r1]=va1.y; As[0][kq1*4+2][r1]=va1.z; As[0][kq1*4+3][r1]=va1.w;
        Bs[0][kq1*4+0][r1]=vb1.x; Bs[0][kq1*4+1][r1]=vb1.y; Bs[0][kq1*4+2][r1]=vb1.z; Bs[0][kq1*4+3][r1]=vb1.w;
    }
    __syncthreads();

    const int NT = Ez / 16;   // 32 tiles
    for (int it = 0; it < NT; it++) {
        int cur = it & 1;
        float4 va0, vb0, va1, vb1;
        bool more = (it + 1 < NT);
        if (more) {
            int kt = (it + 1) * 16;
            va0 = *(const float4*)(A  + r0 * Ez + kt + kq0 * 4);
            vb0 = *(const float4*)(Bp + r0 * Ez + kt + kq0 * 4);
            va1 = *(const float4*)(A  + r1 * Ez + kt + kq1 * 4);
            vb1 = *(const float4*)(Bp + r1 * Ez + kt + kq1 * 4);
        }
        #pragma unroll
        for (int k = 0; k < 16; k++) {
            float ra[8], rb[8];
            *(float4*)&ra[0] = *(const float4*)&As[cur][k][ty * 8];
            *(float4*)&ra[4] = *(const float4*)&As[cur][k][ty * 8 + 4];
            *(float4*)&rb[0] = *(const float4*)&Bs[cur][k][tx * 8];
            *(float4*)&rb[4] = *(const float4*)&Bs[cur][k][tx * 8 + 4];
            #pragma unroll
            for (int i = 0; i < 8; i++)
                #pragma unroll
                for (int j = 0; j < 8; j++) acc[i][j] += ra[i] * rb[j];
        }
        if (more) {
            int nxt = cur ^ 1;
            As[nxt][kq0*4+0][r0]=va0.x; As[nxt][kq0*4+1][r0]=va0.y; As[nxt][kq0*4+2][r0]=va0.z; As[nxt][kq0*4+3][r0]=va0.w;
            Bs[nxt][kq0*4+0][r0]=vb0.x; Bs[nxt][kq0*4+1][r0]=vb0.y; Bs[nxt][kq0*4+2][r0]=vb0.z; Bs[nxt][kq0*4+3][r0]=vb0.w;
            As[nxt][kq1*4+0][r1]=va1.x; As[nxt][kq1*4+1][r1]=va1.y; As[nxt][kq1*4+2][r1]=va1.z; As[nxt][kq1*4+3][r1]=va1.w;
            Bs[nxt][kq1*4+0][r1]=vb1.x; Bs[nxt][kq1*4+1][r1]=vb1.y; Bs[nxt][kq1*4+2][r1]=vb1.z; Bs[nxt][kq1*4+3][r1]=vb1.w;
            __syncthreads();
        }
    }

    int n0 = bn * 128 + tx * 8;
    float bias[8];
    #pragma unroll
    for (int j = 0; j < 8; j++) bias[j] = bu[n0 + j];
    #pragma unroll
    for (int i = 0; i < 8; i++) {
        int m = bm * 128 + ty * 8 + i;            // m = t*B + b
        int t = m / Bz, b = m % Bz;
        float* dst = out + (size_t)b * (Tz * Vz) + (size_t)t * Vz + n0;
        float4 v0 = make_float4(acc[i][0]+bias[0], acc[i][1]+bias[1],
                                acc[i][2]+bias[2], acc[i][3]+bias[3]);
        float4 v1 = make_float4(acc[i][4]+bias[4], acc[i][5]+bias[5],
                                acc[i][6]+bias[6], acc[i][7]+bias[7]);
        *(float4*)dst = v0;
        *(float4*)(dst + 4) = v1;
    }
}

// ---------------- host ---------------------------------------------------------
extern "C" void kernel_launch(void* const* d_in, const int* in_sizes, int n_in,
                              void* d_out, int out_size)
{
    const float* latent = (const float*)d_in[1];
    const float* Wi     = (const float*)d_in[2];
    const float* bi     = (const float*)d_in[3];
    const float* Wh     = (const float*)d_in[4];
    const float* bh     = (const float*)d_in[5];
    const float* Wp     = (const float*)d_in[6];
    const float* bp     = (const float*)d_in[7];
    const float* W_lh   = (const float*)d_in[8];
    const float* b_lh   = (const float*)d_in[9];
    const float* Wo     = (const float*)d_in[10];
    const float* bo     = (const float*)d_in[11];
    const float* Wu     = (const float*)d_in[12];
    const float* bu     = (const float*)d_in[13];
    const float* start  = (const float*)d_in[14];
    float* out = (float*)d_out;

    seed_kernel<<<96, 256>>>(start, out);
    init_kernel<<<64, 256>>>(latent, W_lh, b_lh, Wp, bp);

    for (int s = 0; s < Tz - 1; s++) {
        gates_kernel<<<dim3(48, NPART), 256>>>(s, Wi, Wh);
        hy_kernel<<<192, 256>>>(s, bi, bh);
        outp_kernel<<<dim3(9, 8), 256>>>(s, Wo);
        reduce_kernel<<<97, 256>>>(s, bo, out);
    }

    unembed_kernel<<<dim3(Vz / 128, (Tz * Bz) / 128), 256>>>(Wu, bu, out);
}

// round 5
// speedup vs baseline: 1.3140x; 1.3140x over previous
#include <cuda_runtime.h>
#include <math.h>

#define Bz  48
#define Ez  512
#define Hz  1024
#define Vz  32000
#define Tz  64
#define G3  3072            // 3*H
#define EP1 513             // E+1
#define OPLD 520            // padded ld for o partials
#define BTV (Bz*Tz*Vz)      // 98,304,000
#define NPART 12            // gate split-K parts: 4 for ig (K=128 ea), 8 for hg (K=128 ea)

// ---------------- scratch (static device memory, no allocation) ----------------
__device__ float g_emb[Tz * Bz * Ez];        // emb_t for t=0..63   (6.29 MB)
__device__ float g_h[2][Bz * Hz];            // hidden ping-pong
__device__ float g_peep[Bz * G3];            // latent @ Wp^T + bp  (constant over t)
__device__ float g_gpart[NPART][Bz * G3];    // split-K gate partials (7.1 MB)
__device__ float g_opart[8 * Bz * OPLD];     // split-K partials for o

__device__ __forceinline__ float sigmoidf_(float x) { return 1.f / (1.f + expf(-x)); }

__device__ __forceinline__ unsigned f2tf32(float f) {
    unsigned r;
    asm("cvt.rna.tf32.f32 %0, %1;" : "=r"(r) : "f"(f));
    return r;
}

// ---------------- generic 48xN small GEMM tile (M=48 full, tile N=64, BK=16) ----
struct __align__(16) SmemGemm { float As[16][52]; float Ws[16][68]; };

__device__ __forceinline__ void gemm48_tile(
    SmemGemm& sm,
    const float* __restrict__ A, int lda,
    const float* __restrict__ W, int ldw,
    float* __restrict__ C, int ldc,
    const float* __restrict__ bias,
    int N, int n0, int k0, int kc)
{
    int tid = threadIdx.x;
    int tx = tid & 15, ty = tid >> 4;
    float acc[3][4] = {{0.f,0.f,0.f,0.f},{0.f,0.f,0.f,0.f},{0.f,0.f,0.f,0.f}};

    for (int kk = 0; kk < kc; kk += 16) {
        if (tid < 192) {                         // A tile: 48 rows x 16 k
            int r = tid >> 2, kq = tid & 3;
            float4 v = *(const float4*)(A + r * lda + k0 + kk + kq * 4);
            sm.As[kq*4+0][r] = v.x; sm.As[kq*4+1][r] = v.y;
            sm.As[kq*4+2][r] = v.z; sm.As[kq*4+3][r] = v.w;
        }
        {                                        // W tile: 64 rows x 16 k
            int n = tid >> 2, kq = tid & 3;
            int gn = n0 + n;
            float4 v = make_float4(0.f, 0.f, 0.f, 0.f);
            if (gn < N) v = *(const float4*)(W + gn * ldw + k0 + kk + kq * 4);
            sm.Ws[kq*4+0][n] = v.x; sm.Ws[kq*4+1][n] = v.y;
            sm.Ws[kq*4+2][n] = v.z; sm.Ws[kq*4+3][n] = v.w;
        }
        __syncthreads();
        #pragma unroll
        for (int k = 0; k < 16; k++) {
            float a0 = sm.As[k][ty], a1 = sm.As[k][ty+16], a2 = sm.As[k][ty+32];
            float4 bv = *(const float4*)&sm.Ws[k][tx * 4];
            acc[0][0] += a0*bv.x; acc[0][1] += a0*bv.y; acc[0][2] += a0*bv.z; acc[0][3] += a0*bv.w;
            acc[1][0] += a1*bv.x; acc[1][1] += a1*bv.y; acc[1][2] += a1*bv.z; acc[1][3] += a1*bv.w;
            acc[2][0] += a2*bv.x; acc[2][1] += a2*bv.y; acc[2][2] += a2*bv.z; acc[2][3] += a2*bv.w;
        }
        __syncthreads();
    }
    #pragma unroll
    for (int i = 0; i < 3; i++) {
        int r = ty + i * 16;
        #pragma unroll
        for (int j = 0; j < 4; j++) {
            int n = n0 + tx * 4 + j;
            if (n < N) {
                float v = acc[i][j];
                if (bias) v += bias[n];
                C[r * ldc + n] = v;
            }
        }
    }
}

// ---------------- kernels ------------------------------------------------------

// emb_0 = start broadcast; stops[:,0] = 0
__global__ void seed_kernel(const float* __restrict__ start, float* __restrict__ out)
{
    int idx = blockIdx.x * 256 + threadIdx.x;
    if (idx < Bz * Ez) g_emb[idx] = start[idx & (Ez - 1)];
    if (idx < Bz) out[BTV + idx * Tz] = 0.f;
}

// h0 = latent @ W_lh^T + b_lh ; peep = latent @ Wp^T + bp
__global__ void init_kernel(const float* __restrict__ latent,
                            const float* __restrict__ W_lh, const float* __restrict__ b_lh,
                            const float* __restrict__ Wp,   const float* __restrict__ bp)
{
    __shared__ SmemGemm sm;
    if (blockIdx.x < 16)
        gemm48_tile(sm, latent, Hz, W_lh, Hz, g_h[0], Hz, b_lh, Hz, blockIdx.x * 64, 0, Hz);
    else
        gemm48_tile(sm, latent, Hz, Wp, Hz, g_peep, G3, bp, G3, (blockIdx.x - 16) * 64, 0, Hz);
}

// split-K gate partials: p<4 -> ig (K=512 in 4 chunks), p>=4 -> hg (K=1024 in 8 chunks)
__global__ void gates_kernel(int s, const float* __restrict__ Wi, const float* __restrict__ Wh)
{
    __shared__ SmemGemm sm;
    int p = blockIdx.y;
    int n0 = blockIdx.x * 64;
    if (p < 4)
        gemm48_tile(sm, g_emb + s * Bz * Ez, Ez, Wi, Ez,
                    g_gpart[p], G3, nullptr, G3, n0, p * 128, 128);
    else
        gemm48_tile(sm, g_h[s & 1], Hz, Wh, Hz,
                    g_gpart[p], G3, nullptr, G3, n0, (p - 4) * 128, 128);
}

// gate elementwise: reduce partials, compute hy -> h_new
__global__ void hy_kernel(int s, const float* __restrict__ bi, const float* __restrict__ bh)
{
    int idx = blockIdx.x * 256 + threadIdx.x;    // 48*1024 exactly
    int b = idx >> 10, j = idx & 1023;
    const float* h_prev = g_h[s & 1];
    float* h_new = g_h[(s + 1) & 1];
    int base = b * G3;
    float ir = bi[j], ii = bi[Hz + j], in_ = bi[2*Hz + j];
    #pragma unroll
    for (int p = 0; p < 4; p++) {
        ir  += g_gpart[p][base + j];
        ii  += g_gpart[p][base + Hz + j];
        in_ += g_gpart[p][base + 2*Hz + j];
    }
    float hr = bh[j], hi = bh[Hz + j], hn = bh[2*Hz + j];
    #pragma unroll
    for (int p = 4; p < 12; p++) {
        hr += g_gpart[p][base + j];
        hi += g_gpart[p][base + Hz + j];
        hn += g_gpart[p][base + 2*Hz + j];
    }
    float pr = g_peep[base + j], pi = g_peep[base + Hz + j], pn = g_peep[base + 2*Hz + j];
    float r  = sigmoidf_(ir + hr + pr);
    float zi = sigmoidf_(ii + hi + pi);
    float n  = tanhf(in_ + r * hn + pn);
    float h  = h_prev[idx];
    h_new[idx] = n + zi * (h - n);
}

// o = hy @ Wo^T (split-K 8 x 128) -> partials
__global__ void outp_kernel(int s, const float* __restrict__ Wo)
{
    __shared__ SmemGemm sm;
    int kc = blockIdx.y;                          // 0..7
    gemm48_tile(sm, g_h[(s + 1) & 1], Hz, Wo, Hz,
                g_opart + kc * Bz * OPLD, OPLD, nullptr, EP1,
                blockIdx.x * 64, kc * 128, 128);
}

// reduce o partials + bo; tanh -> emb_{s+1}, sigmoid -> stop_{s+1}
__global__ void reduce_kernel(int s, const float* __restrict__ bo, float* __restrict__ out)
{
    int idx = blockIdx.x * 256 + threadIdx.x;
    if (idx >= Bz * EP1) return;
    int b = idx / EP1, n = idx % EP1;
    float v = bo[n];
    #pragma unroll
    for (int k = 0; k < 8; k++) v += g_opart[k * Bz * OPLD + b * OPLD + n];
    int t = s + 1;
    if (n < Ez) g_emb[(t * Bz + b) * Ez + n] = tanhf(v);
    else        out[BTV + b * Tz + t] = sigmoidf_(v);
}

// ---------------- unembed: tf32 tensor-core GEMM -------------------------------
// logits: (T*B=3072, E=512) @ Wu^T (V=32000) + bu -> out in (B,T,V) layout.
// Block tile 128x128, 8 warps (2x4), warp tile 64x32, mma.m16n8k8 tf32.
// Smem k-major tf32, pad 136 -> conflict-free fragment loads. Double-buffered.
__global__ void __launch_bounds__(256) unembed_kernel(
    const float* __restrict__ Wu, const float* __restrict__ bu, float* __restrict__ out)
{
    __shared__ unsigned As[2][16][136];
    __shared__ unsigned Bs[2][16][136];

    int tid  = threadIdx.x;
    int warp = tid >> 5, lane = tid & 31;
    int wm = warp >> 2, wn = warp & 3;            // 2 x 4 warp grid
    int m_warp = wm * 64, n_warp = wn * 32;
    int gID = lane >> 2, tig = lane & 3;

    const float* A  = g_emb + (size_t)blockIdx.y * 128 * Ez;
    const float* Bp = Wu    + (size_t)blockIdx.x * 128 * Ez;

    // loader coords: rows r0 and r0+64, 4 consecutive k at kq*4
    int r0 = tid >> 2, kq = tid & 3;

    float acc[4][4][4];
    #pragma unroll
    for (int mt = 0; mt < 4; mt++)
        #pragma unroll
        for (int nt = 0; nt < 4; nt++)
            #pragma unroll
            for (int c = 0; c < 4; c++) acc[mt][nt][c] = 0.f;

    // ---- preload stage 0 ----
    {
        #pragma unroll
        for (int u = 0; u < 2; u++) {
            int r = r0 + u * 64;
            float4 va = *(const float4*)(A  + r * Ez + kq * 4);
            float4 vb = *(const float4*)(Bp + r * Ez + kq * 4);
            As[0][kq*4+0][r] = f2tf32(va.x); As[0][kq*4+1][r] = f2tf32(va.y);
            As[0][kq*4+2][r] = f2tf32(va.z); As[0][kq*4+3][r] = f2tf32(va.w);
            Bs[0][kq*4+0][r] = f2tf32(vb.x); Bs[0][kq*4+1][r] = f2tf32(vb.y);
            Bs[0][kq*4+2][r] = f2tf32(vb.z); Bs[0][kq*4+3][r] = f2tf32(vb.w);
        }
    }
    __syncthreads();

    const int NT = Ez / 16;                       // 32 stages
    for (int it = 0; it < NT; it++) {
        int cur = it & 1;
        float4 va[2], vb[2];
        bool more = (it + 1 < NT);
        if (more) {
            int kt = (it + 1) * 16;
            #pragma unroll
            for (int u = 0; u < 2; u++) {
                int r = r0 + u * 64;
                va[u] = *(const float4*)(A  + r * Ez + kt + kq * 4);
                vb[u] = *(const float4*)(Bp + r * Ez + kt + kq * 4);
            }
        }

        #pragma unroll
        for (int ks = 0; ks < 2; ks++) {
            int k0 = ks * 8;
            unsigned a[4][4];
            #pragma unroll
            for (int mt = 0; mt < 4; mt++) {
                int m0 = m_warp + mt * 16;
                a[mt][0] = As[cur][k0 + tig    ][m0 + gID    ];
                a[mt][1] = As[cur][k0 + tig    ][m0 + gID + 8];
                a[mt][2] = As[cur][k0 + tig + 4][m0 + gID    ];
                a[mt][3] = As[cur][k0 + tig + 4][m0 + gID + 8];
            }
            unsigned b[4][2];
            #pragma unroll
            for (int nt = 0; nt < 4; nt++) {
                int n0 = n_warp + nt * 8;
                b[nt][0] = Bs[cur][k0 + tig    ][n0 + gID];
                b[nt][1] = Bs[cur][k0 + tig + 4][n0 + gID];
            }
            #pragma unroll
            for (int mt = 0; mt < 4; mt++)
                #pragma unroll
                for (int nt = 0; nt < 4; nt++) {
                    asm volatile(
                        "mma.sync.aligned.m16n8k8.row.col.f32.tf32.tf32.f32 "
                        "{%0,%1,%2,%3}, {%4,%5,%6,%7}, {%8,%9}, {%0,%1,%2,%3};"
                        : "+f"(acc[mt][nt][0]), "+f"(acc[mt][nt][1]),
                          "+f"(acc[mt][nt][2]), "+f"(acc[mt][nt][3])
                        : "r"(a[mt][0]), "r"(a[mt][1]), "r"(a[mt][2]), "r"(a[mt][3]),
                          "r"(b[nt][0]), "r"(b[nt][1]));
                }
        }

        if (more) {
            int nxt = cur ^ 1;
            #pragma unroll
            for (int u = 0; u < 2; u++) {
                int r = r0 + u * 64;
                As[nxt][kq*4+0][r] = f2tf32(va[u].x); As[nxt][kq*4+1][r] = f2tf32(va[u].y);
                As[nxt][kq*4+2][r] = f2tf32(va[u].z); As[nxt][kq*4+3][r] = f2tf32(va[u].w);
                Bs[nxt][kq*4+0][r] = f2tf32(vb[u].x); Bs[nxt][kq*4+1][r] = f2tf32(vb[u].y);
                Bs[nxt][kq*4+2][r] = f2tf32(vb[u].z); Bs[nxt][kq*4+3][r] = f2tf32(vb[u].w);
            }
            __syncthreads();
        }
    }

    // ---- epilogue: bias + direct stores ----
    #pragma unroll
    for (int nt = 0; nt < 4; nt++) {
        int col = blockIdx.x * 128 + n_warp + nt * 8 + 2 * tig;
        float bv0 = bu[col], bv1 = bu[col + 1];
        #pragma unroll
        for (int mt = 0; mt < 4; mt++) {
            int m_lo = blockIdx.y * 128 + m_warp + mt * 16 + gID;
            #pragma unroll
            for (int half = 0; half < 2; half++) {
                int m = m_lo + half * 8;
                int t = m / Bz, b = m % Bz;
                float* dst = out + (size_t)b * (Tz * Vz) + (size_t)t * Vz + col;
                float2 v = make_float2(acc[mt][nt][half*2+0] + bv0,
                                       acc[mt][nt][half*2+1] + bv1);
                *(float2*)dst = v;
            }
        }
    }
}

// ---------------- host ---------------------------------------------------------
extern "C" void kernel_launch(void* const* d_in, const int* in_sizes, int n_in,
                              void* d_out, int out_size)
{
    const float* latent = (const float*)d_in[1];
    const float* Wi     = (const float*)d_in[2];
    const float* bi     = (const float*)d_in[3];
    const float* Wh     = (const float*)d_in[4];
    const float* bh     = (const float*)d_in[5];
    const float* Wp     = (const float*)d_in[6];
    const float* bp     = (const float*)d_in[7];
    const float* W_lh   = (const float*)d_in[8];
    const float* b_lh   = (const float*)d_in[9];
    const float* Wo     = (const float*)d_in[10];
    const float* bo     = (const float*)d_in[11];
    const float* Wu     = (const float*)d_in[12];
    const float* bu     = (const float*)d_in[13];
    const float* start  = (const float*)d_in[14];
    float* out = (float*)d_out;

    seed_kernel<<<96, 256>>>(start, out);
    init_kernel<<<64, 256>>>(latent, W_lh, b_lh, Wp, bp);

    for (int s = 0; s < Tz - 1; s++) {
        gates_kernel<<<dim3(48, NPART), 256>>>(s, Wi, Wh);
        hy_kernel<<<192, 256>>>(s, bi, bh);
        outp_kernel<<<dim3(9, 8), 256>>>(s, Wo);
        reduce_kernel<<<97, 256>>>(s, bo, out);
    }

    unembed_kernel<<<dim3(Vz / 128, (Tz * Bz) / 128), 256>>>(Wu, bu, out);
}